// round 15
// baseline (speedup 1.0000x reference)
#include <cuda_runtime.h>
#include <math.h>

#define H 512
#define W 512
#define PLANE (H*W)
#define NB 8
#define NPL 16
#define NELEM (NB*PLANE)
#define EPSF 1e-6f
#define BIG 1e30f

// 2-col-per-thread skeletonize layout: 56 useful cols per warp, 16 rows per seg
#define STRIPSP 10
#define SEGSP   32
#define SEGH    16
#define BLK_WARPS 4
#define WARPS_PLANE (STRIPSP*SEGSP)            // 320 warps per plane
#define GRIDC  (4*WARPS_PLANE/BLK_WARPS)       // 320 blocks per chain launch (4 planes)

__device__ float g_bufA[NPL*PLANE];
__device__ float g_bufB[NPL*PLANE];
__device__ float g_skel[NPL*PLANE];
__device__ float g_acc[96];

// fast sigmoid: sigmoid(x) = 0.5*tanh(x/2) + 0.5  (MUFU.TANH, sm_75+)
__device__ __forceinline__ float sigmoidf_(float x) {
    float t;
    asm("tanh.approx.f32 %0, %1;" : "=f"(t) : "f"(0.5f * x));
    return fmaf(0.5f, t, 0.5f);
}

__device__ __forceinline__ float focal_elem(float x, float t) {
    float e = __expf(-fabsf(x));
    float bce = fmaxf(x, 0.0f) - x * t + __logf(1.0f + e);
    float p   = sigmoidf_(x);
    float pt  = p * t + (1.0f - p) * (1.0f - t);
    float at  = 0.25f * t + 0.75f * (1.0f - t);
    float om  = 1.0f - pt;
    return at * om * om * bce;
}

__device__ __forceinline__ float blk_sum(float v, float* sh) {
    int tid = threadIdx.x;
    #pragma unroll
    for (int o = 16; o > 0; o >>= 1) v += __shfl_down_sync(0xffffffffu, v, o);
    if ((tid & 31) == 0) sh[tid >> 5] = v;
    __syncthreads();
    float r = 0.0f;
    if (tid < 32) {
        r = (tid < (int)(blockDim.x >> 5)) ? sh[tid] : 0.0f;
        #pragma unroll
        for (int o = 16; o > 0; o >>= 1) r += __shfl_down_sync(0xffffffffu, r, o);
    }
    __syncthreads();
    return r;
}

// pairwise 5-pt cross erode over 64 warp columns (cols x0=2*lane, x1=2*lane+1)
__device__ __forceinline__ float2 erode5p(float2 m, float2 c, float2 p) {
    float lm = __shfl_up_sync(0xffffffffu, c.y, 1);
    float rm = __shfl_down_sync(0xffffffffu, c.x, 1);
    float2 r;
    r.x = fminf(fminf(fminf(m.x, p.x), c.x), fminf(lm, c.y));
    r.y = fminf(fminf(fminf(m.y, p.y), c.y), fminf(c.x, rm));
    return r;
}
// pairwise 3x3 max (open)
__device__ __forceinline__ float2 open3p(float2 m, float2 c, float2 p) {
    float2 v;
    v.x = fmaxf(fmaxf(m.x, p.x), c.x);
    v.y = fmaxf(fmaxf(m.y, p.y), c.y);
    float lm = __shfl_up_sync(0xffffffffu, v.y, 1);
    float rm = __shfl_down_sync(0xffffffffu, v.x, 1);
    float2 r;
    r.x = fmaxf(v.x, fmaxf(lm, v.y));
    r.y = fmaxf(v.y, fmaxf(v.x, rm));
    return r;
}
__device__ __forceinline__ float2 padv(float2 v, bool rowOK, bool x0OK, bool x1OK, float pad) {
    float2 r;
    r.x = (rowOK && x0OK) ? v.x : pad;
    r.y = (rowOK && x1OK) ? v.y : pad;
    return r;
}

__global__ void zero_acc_kernel() {
    if (threadIdx.x < 96) g_acc[threadIdx.x] = 0.0f;
}

// ---------------------------------------------------------------------------
// Pass A for ONE batch (float4-vectorized); seeds g_bufA planes b and 8+b.
// ---------------------------------------------------------------------------
__global__ void pass_a_kernel(const float4* __restrict__ ml, const float4* __restrict__ sl,
                              const float4* __restrict__ ul, const float4* __restrict__ jl,
                              const float4* __restrict__ el, const float4* __restrict__ ap,
                              const float4* __restrict__ mk, const float4* __restrict__ sk,
                              const float4* __restrict__ jn, const float4* __restrict__ ep,
                              const float4* __restrict__ at, const float4* __restrict__ un,
                              int b) {
    const int Q = PLANE / 4;
    int tid = threadIdx.x;
    int base = b * Q;

    float4* __restrict__ bufap = (float4*)g_bufA;

    float di = 0.f, dp = 0.f, dt = 0.f;
    float si = 0.f, spp = 0.f, stt = 0.f;
    float fm = 0.f, fj = 0.f, fe = 0.f;
    float sl1 = 0.f, msum = 0.f, usum = 0.f;

    for (int i = blockIdx.x * blockDim.x + tid; i < Q; i += gridDim.x * blockDim.x) {
        int g = base + i;
        float4 xm4 = ml[g];
        float4 tm4 = mk[g];
        float4 pm4, tmc4;

        #pragma unroll
        for (int u = 0; u < 4; u++) {
            float xm = ((float*)&xm4)[u];
            float tm = ((float*)&tm4)[u];
            float pm = sigmoidf_(xm);
            ((float*)&pm4)[u] = pm;
            ((float*)&tmc4)[u] = fminf(fmaxf(tm, 0.0f), 1.0f);
            di += pm * tm;  dp += pm;  dt += tm;
            fm += focal_elem(xm, tm);
        }
        bufap[g] = pm4;
        bufap[(8 + b) * Q + i] = tmc4;

        float4 ts4 = sk[g];
        float4 ps4 = sl[g];
        float4 jl4 = jl[g], jn4 = jn[g], el4 = el[g], ep4 = ep[g];
        float4 ul4 = ul[g], un4 = un[g];
        float4 ap0 = ap[b * 2 * Q + i], ap1 = ap[b * 2 * Q + Q + i];
        float4 at0 = at[b * 2 * Q + i], at1 = at[b * 2 * Q + Q + i];

        #pragma unroll
        for (int u = 0; u < 4; u++) {
            float ts = ((float*)&ts4)[u];
            float psk = sigmoidf_(((float*)&ps4)[u]);
            si += psk * ts;  spp += psk;  stt += ts;

            fj += focal_elem(((float*)&jl4)[u], ((float*)&jn4)[u]);
            fe += focal_elem(((float*)&el4)[u], ((float*)&ep4)[u]);

            float pu = sigmoidf_(((float*)&ul4)[u]);
            float du = pu - ((float*)&un4)[u];
            usum += du * du;

            float m = ts;
            float d0 = ((float*)&ap0)[u] * m - ((float*)&at0)[u] * m;
            float ad0 = fabsf(d0);
            sl1 += (ad0 < 1.0f) ? 0.5f * d0 * d0 : ad0 - 0.5f;
            float d1 = ((float*)&ap1)[u] * m - ((float*)&at1)[u] * m;
            float ad1 = fabsf(d1);
            sl1 += (ad1 < 1.0f) ? 0.5f * d1 * d1 : ad1 - 0.5f;
            msum += 2.0f * m;
        }
    }

    __shared__ float sh[32];
    float vals[12] = {di, dp, dt, si, spp, stt, fm, fj, fe, sl1, msum, usum};
    #pragma unroll
    for (int k = 0; k < 12; k++) {
        float r = blk_sum(vals[k], sh);
        if (tid == 0) {
            int a = (k < 6) ? (b * 6 + k) : (42 + k);
            atomicAdd(&g_acc[a], r);
        }
    }
}

// ---------------------------------------------------------------------------
// Fused double-iteration skeletonize, 2 columns per thread.
// Each launch covers FOUR planes: {pb, pb+1, pb+8, pb+9} (batches pb, pb+1).
//  MODE 0: init + iters 1,2  (skel pure write)
//  MODE 1: two iterations     (skel RMW)
//  MODE 2: final two iters + clDice accumulation (no global writes)
// s-update: s += fmaf(-s, d, d)  (relu dropped: provably >= 0 for s,d in [0,1])
// ---------------------------------------------------------------------------
template<int MODE>
__global__ void __launch_bounds__(128, 9) skel2_kernel(int useA, int pb,
                                                       const float* __restrict__ ml,
                                                       const float* __restrict__ mk) {
    const float* __restrict__ cur = useA ? g_bufA : g_bufB;
    float* __restrict__ nxt = useA ? g_bufB : g_bufA;

    int lane = threadIdx.x & 31;
    int wg = blockIdx.x * BLK_WARPS + (threadIdx.x >> 5);
    int q = wg / WARPS_PLANE;               // 0..3
    int plane = pb + (q & 1) + (q >> 1) * 8;
    int rem = wg - q * WARPS_PLANE;
    int strip = rem / SEGSP;
    int seg = rem & (SEGSP - 1);

    int x0 = strip * 56 - 4 + 2 * lane;
    int x1 = x0 + 1;
    bool x0OK = (unsigned)x0 < (unsigned)W;
    bool x1OK = (unsigned)x1 < (unsigned)W;
    bool laneOut = (lane >= 2) && (lane <= 29);
    bool out0 = laneOut && x0OK;
    bool out1 = laneOut && x1OK;
    int y0 = seg * SEGH;
    int base = plane * PLANE;

    const float* __restrict__ cp = cur + base + x0;
    float* __restrict__ skp = g_skel + base + x0;
    float* __restrict__ nxp = nxt + base + x0;

    bool isPred = (q < 2);
    int b8 = pb + (q & 1);
    const float* __restrict__ pp = (isPred ? mk : ml) + b8 * PLANE + x0;
    float accP = 0.0f, accS = 0.0f;

    bool fast = (strip >= 1) && (strip <= 8) && (seg >= 1) && (seg <= 30);

    float2 c0, c1, c2, c3, c4, c5;
    float2 e1_m, e1_0, e1_1, e1_2;
    float2 e2_m, e2_0, e2_1;
    float2 e3_m, e3_0;

    if (fast) {
        float2 c_[10];
        #pragma unroll
        for (int i = 0; i < 10; i++) c_[i] = *(const float2*)(cp + (y0 - 4 + i) * W);
        float2 e1r[6];
        #pragma unroll
        for (int k = 0; k < 6; k++) e1r[k] = erode5p(c_[k], c_[k + 1], c_[k + 2]);
        float2 e2r[4];
        #pragma unroll
        for (int k = 0; k < 4; k++) e2r[k] = erode5p(e1r[k], e1r[k + 1], e1r[k + 2]);
        e3_m = erode5p(e2r[0], e2r[1], e2r[2]);
        e3_0 = erode5p(e2r[1], e2r[2], e2r[3]);

        c0 = c_[4]; c1 = c_[5]; c2 = c_[6]; c3 = c_[7]; c4 = c_[8]; c5 = c_[9];
        e1_m = e1r[2]; e1_0 = e1r[3]; e1_1 = e1r[4]; e1_2 = e1r[5];
        e2_m = e2r[1]; e2_0 = e2r[2]; e2_1 = e2r[3];

        #pragma unroll 4
        for (int y = y0; y < y0 + SEGH; y++) {
            float2 c6 = *(const float2*)(cp + (y + 6) * W);
            float2 e1_3 = erode5p(c2, c3, c4);
            float2 e2_2 = erode5p(e1_1, e1_2, e1_3);
            float2 e3_1 = erode5p(e2_0, e2_1, e2_2);

            float2 openA = open3p(e2_m, e2_0, e2_1);
            float2 openB = open3p(e3_m, e3_0, e3_1);

            float2 s;
            if (MODE == 0) {
                float2 openI = open3p(e1_m, e1_0, e1_1);
                s.x = fmaxf(c0.x - openI.x, 0.0f);
                s.y = fmaxf(c0.y - openI.y, 0.0f);
            } else {
                s = *(const float2*)(skp + y * W);
            }
            float dA0 = fmaxf(e1_0.x - openA.x, 0.0f);
            float dA1 = fmaxf(e1_0.y - openA.y, 0.0f);
            s.x += fmaf(-s.x, dA0, dA0);
            s.y += fmaf(-s.y, dA1, dA1);
            float dB0 = fmaxf(e2_0.x - openB.x, 0.0f);
            float dB1 = fmaxf(e2_0.y - openB.y, 0.0f);
            s.x += fmaf(-s.x, dB0, dB0);
            s.y += fmaf(-s.y, dB1, dB1);

            if (MODE == 2) {
                if (laneOut) {
                    float2 t = *(const float2*)(pp + y * W);
                    float t0 = isPred ? fminf(fmaxf(t.x, 0.0f), 1.0f) : sigmoidf_(t.x);
                    float t1 = isPred ? fminf(fmaxf(t.y, 0.0f), 1.0f) : sigmoidf_(t.y);
                    float ps0 = fminf(fmaxf(s.x, 0.0f), 1.0f);
                    float ps1 = fminf(fmaxf(s.y, 0.0f), 1.0f);
                    accP += ps0 * t0 + ps1 * t1;
                    accS += ps0 + ps1;
                }
            } else if (laneOut) {
                *(float2*)(nxp + y * W) = e2_0;
                *(float2*)(skp + y * W) = s;
            }

            if (MODE == 0) { c0 = c1; c1 = c2; }
            c2 = c3; c3 = c4; c4 = c5; c5 = c6;
            if (MODE == 0) e1_m = e1_0;
            e1_0 = e1_1; e1_1 = e1_2; e1_2 = e1_3;
            e2_m = e2_0; e2_0 = e2_1; e2_1 = e2_2;
            e3_m = e3_0; e3_0 = e3_1;
        }
    } else {
        // ---------------- general (boundary) path ----------------
        float2 c_[10];
        #pragma unroll
        for (int i = 0; i < 10; i++) {
            int yy = y0 - 4 + i;
            bool rOK = (unsigned)yy < (unsigned)H;
            float2 v;
            v.x = (rOK && x0OK) ? cp[yy * W] : BIG;
            v.y = (rOK && x1OK) ? cp[yy * W + 1] : BIG;
            c_[i] = v;
        }
        float2 e1r[6];
        #pragma unroll
        for (int k = 0; k < 6; k++) {
            int r = y0 - 3 + k;
            e1r[k] = padv(erode5p(c_[k], c_[k + 1], c_[k + 2]),
                          (unsigned)r < (unsigned)H, x0OK, x1OK, BIG);
        }
        float2 e2r[4];
        #pragma unroll
        for (int k = 0; k < 4; k++) e2r[k] = erode5p(e1r[k], e1r[k + 1], e1r[k + 2]);

        float2 t0v = padv(e2r[0], (y0 - 2) >= 0, x0OK, x1OK, BIG);
        float2 t1v = padv(e2r[1], (y0 - 1) >= 0, x0OK, x1OK, BIG);
        float2 t2v = padv(e2r[2], true, x0OK, x1OK, BIG);
        float2 t3v = padv(e2r[3], true, x0OK, x1OK, BIG);
        e3_m = padv(erode5p(t0v, t1v, t2v), (y0 - 1) >= 0, x0OK, x1OK, -BIG);
        e3_0 = padv(erode5p(t1v, t2v, t3v), true, x0OK, x1OK, -BIG);

        c0 = c_[4]; c1 = c_[5]; c2 = c_[6]; c3 = c_[7]; c4 = c_[8]; c5 = c_[9];
        e1_m = e1r[2]; e1_0 = e1r[3]; e1_1 = e1r[4]; e1_2 = e1r[5];
        e2_m = e2r[1]; e2_0 = e2r[2]; e2_1 = e2r[3];

        #pragma unroll 4
        for (int y = y0; y < y0 + SEGH; y++) {
            int yl = y + 6;
            bool rl = (unsigned)yl < (unsigned)H;
            float2 c6;
            c6.x = (rl && x0OK) ? cp[yl * W] : BIG;
            c6.y = (rl && x1OK) ? cp[yl * W + 1] : BIG;

            float2 e1_3 = padv(erode5p(c2, c3, c4), (unsigned)(y + 3) < (unsigned)H, x0OK, x1OK, BIG);
            float2 e2_2 = erode5p(e1_1, e1_2, e1_3);

            float2 a = padv(e2_0, true, x0OK, x1OK, BIG);
            float2 b = padv(e2_1, (unsigned)(y + 1) < (unsigned)H, x0OK, x1OK, BIG);
            float2 d = padv(e2_2, (unsigned)(y + 2) < (unsigned)H, x0OK, x1OK, BIG);
            float2 e3_1 = padv(erode5p(a, b, d), (unsigned)(y + 1) < (unsigned)H, x0OK, x1OK, -BIG);

            float2 ma = padv(e2_m, (y - 1) >= 0, x0OK, x1OK, -BIG);
            float2 mb = padv(e2_0, true, x0OK, x1OK, -BIG);
            float2 mc = padv(e2_1, (unsigned)(y + 1) < (unsigned)H, x0OK, x1OK, -BIG);
            float2 openA = open3p(ma, mb, mc);
            float2 openB = open3p(e3_m, e3_0, e3_1);

            float2 s;
            if (MODE == 0) {
                float2 ia = padv(e1_m, (y - 1) >= 0, x0OK, x1OK, -BIG);
                float2 ib = padv(e1_0, true, x0OK, x1OK, -BIG);
                float2 ic = padv(e1_1, (unsigned)(y + 1) < (unsigned)H, x0OK, x1OK, -BIG);
                float2 openI = open3p(ia, ib, ic);
                s.x = fmaxf(c0.x - openI.x, 0.0f);
                s.y = fmaxf(c0.y - openI.y, 0.0f);
            } else {
                s.x = out0 ? skp[y * W] : 0.0f;
                s.y = out1 ? skp[y * W + 1] : 0.0f;
            }
            float dA0 = fmaxf(e1_0.x - openA.x, 0.0f);
            float dA1 = fmaxf(e1_0.y - openA.y, 0.0f);
            s.x += fmaf(-s.x, dA0, dA0);
            s.y += fmaf(-s.y, dA1, dA1);
            float dB0 = fmaxf(e2_0.x - openB.x, 0.0f);
            float dB1 = fmaxf(e2_0.y - openB.y, 0.0f);
            s.x += fmaf(-s.x, dB0, dB0);
            s.y += fmaf(-s.y, dB1, dB1);

            if (MODE == 2) {
                if (out0) {
                    float raw = pp[y * W];
                    float t = isPred ? fminf(fmaxf(raw, 0.0f), 1.0f) : sigmoidf_(raw);
                    float ps = fminf(fmaxf(s.x, 0.0f), 1.0f);
                    accP += ps * t;  accS += ps;
                }
                if (out1) {
                    float raw = pp[y * W + 1];
                    float t = isPred ? fminf(fmaxf(raw, 0.0f), 1.0f) : sigmoidf_(raw);
                    float ps = fminf(fmaxf(s.y, 0.0f), 1.0f);
                    accP += ps * t;  accS += ps;
                }
            } else {
                if (out0) { nxp[y * W] = e2_0.x;      skp[y * W] = s.x; }
                if (out1) { nxp[y * W + 1] = e2_0.y;  skp[y * W + 1] = s.y; }
            }

            c0 = c1; c1 = c2; c2 = c3; c3 = c4; c4 = c5; c5 = c6;
            e1_m = e1_0; e1_0 = e1_1; e1_1 = e1_2; e1_2 = e1_3;
            e2_m = e2_0; e2_0 = e2_1; e2_1 = e2_2;
            e3_m = e3_0; e3_0 = e3_1;
        }
    }

    if (MODE == 2) {
        #pragma unroll
        for (int o = 16; o > 0; o >>= 1) {
            accP += __shfl_down_sync(0xffffffffu, accP, o);
            accS += __shfl_down_sync(0xffffffffu, accS, o);
        }
        if (lane == 0) {
            int idx = 54 + b8 * 4 + (isPred ? 0 : 2);
            atomicAdd(&g_acc[idx], accP);
            atomicAdd(&g_acc[idx + 1], accS);
        }
    }
}

// ---------------------------------------------------------------------------
__global__ void finalize_kernel(float* __restrict__ out) {
    const float N = (float)NELEM;
    float dice_m = 0.f, dice_s = 0.f, cl = 0.f;
    #pragma unroll
    for (int b = 0; b < NB; b++) {
        float im = g_acc[b * 6 + 0], pm = g_acc[b * 6 + 1], tm = g_acc[b * 6 + 2];
        dice_m += (2.0f * im + EPSF) / (pm + tm + EPSF);
        float is = g_acc[b * 6 + 3], ps = g_acc[b * 6 + 4], ts = g_acc[b * 6 + 5];
        dice_s += (2.0f * is + EPSF) / (ps + ts + EPSF);
        float c0 = g_acc[54 + b * 4 + 0], c1 = g_acc[54 + b * 4 + 1];
        float c2 = g_acc[54 + b * 4 + 2], c3 = g_acc[54 + b * 4 + 3];
        float prec = c0 / (c1 + EPSF);
        float sens = c2 / (c3 + EPSF);
        cl += (2.0f * prec * sens + EPSF) / (prec + sens + EPSF);
    }
    dice_m *= 0.125f;  dice_s *= 0.125f;  cl *= 0.125f;

    float mask_loss     = (1.0f - dice_m) + g_acc[48] / N;
    float skeleton_loss = 1.0f - dice_s;
    float topology_loss = 1.0f - cl;
    float node_loss     = 0.5f * (g_acc[49] / N + g_acc[50] / N);
    float msum          = g_acc[52];
    float aff_loss      = (msum == 0.0f) ? 0.0f : g_acc[51] / fmaxf(msum, 1.0f);
    float unc_loss      = g_acc[53] / N;

    out[0] = 1.0f * mask_loss + 1.0f * skeleton_loss + 0.5f * topology_loss +
             0.5f * node_loss + 0.5f * aff_loss + 0.1f * unc_loss;
}

// ---------------------------------------------------------------------------
extern "C" void kernel_launch(void* const* d_in, const int* in_sizes, int n_in,
                              void* d_out, int out_size) {
    const float* ml = (const float*)d_in[0];
    const float* mk = (const float*)d_in[6];
    float* out = (float*)d_out;

    zero_acc_kernel<<<1, 96>>>();

    // ---- fork 4 chains (proven-safe stream count); chain c owns batches 2c, 2c+1 ----
    const int NCH = 4;
    cudaStream_t st[NCH];
    cudaEvent_t evFork, evJoin[NCH];
    cudaEventCreateWithFlags(&evFork, cudaEventDisableTiming);
    cudaEventRecord(evFork, 0);

    for (int c = 0; c < NCH; c++) {
        cudaStreamCreateWithFlags(&st[c], cudaStreamNonBlocking);
        cudaEventCreateWithFlags(&evJoin[c], cudaEventDisableTiming);
        cudaStreamWaitEvent(st[c], evFork, 0);
        int pb = c * 2;

        pass_a_kernel<<<64, 256, 0, st[c]>>>(
            (const float4*)d_in[0], (const float4*)d_in[1], (const float4*)d_in[2],
            (const float4*)d_in[3], (const float4*)d_in[4], (const float4*)d_in[5],
            (const float4*)d_in[6], (const float4*)d_in[7], (const float4*)d_in[8],
            (const float4*)d_in[9], (const float4*)d_in[10], (const float4*)d_in[11], pb);
        pass_a_kernel<<<64, 256, 0, st[c]>>>(
            (const float4*)d_in[0], (const float4*)d_in[1], (const float4*)d_in[2],
            (const float4*)d_in[3], (const float4*)d_in[4], (const float4*)d_in[5],
            (const float4*)d_in[6], (const float4*)d_in[7], (const float4*)d_in[8],
            (const float4*)d_in[9], (const float4*)d_in[10], (const float4*)d_in[11], pb + 1);

        // iters 1,2 (init)  A -> B
        skel2_kernel<0><<<GRIDC, 128, 0, st[c]>>>(1, pb, ml, mk);
        // iters 3,4  B -> A ; 5,6  A -> B ; 7,8  B -> A
        skel2_kernel<1><<<GRIDC, 128, 0, st[c]>>>(0, pb, ml, mk);
        skel2_kernel<1><<<GRIDC, 128, 0, st[c]>>>(1, pb, ml, mk);
        skel2_kernel<1><<<GRIDC, 128, 0, st[c]>>>(0, pb, ml, mk);
        // iters 9,10 + clDice reduce, read A, no writes
        skel2_kernel<2><<<GRIDC, 128, 0, st[c]>>>(1, pb, ml, mk);

        cudaEventRecord(evJoin[c], st[c]);
    }
    for (int c = 0; c < NCH; c++) {
        cudaStreamWaitEvent(0, evJoin[c], 0);
    }

    finalize_kernel<<<1, 1>>>(out);

    for (int c = 0; c < NCH; c++) {
        cudaStreamDestroy(st[c]);
        cudaEventDestroy(evJoin[c]);
    }
    cudaEventDestroy(evFork);
}

// round 16
// speedup vs baseline: 1.1539x; 1.1539x over previous
#include <cuda_runtime.h>
#include <math.h>

#define H 512
#define W 512
#define PLANE (H*W)
#define NB 8
#define NPL 16
#define NELEM (NB*PLANE)
#define EPSF 1e-6f
#define BIG 1e30f

// 2-col-per-thread skeletonize layout: 56 useful cols per warp, 16 rows per seg
#define STRIPSP 10
#define SEGSP   32
#define SEGH    16
#define BLK_WARPS 4
#define PL_CHUNK 4
#define WARPS_PLANE (STRIPSP*SEGSP)            // 320 warps per plane
#define GRIDC  (PL_CHUNK*WARPS_PLANE/BLK_WARPS)  // 320 blocks per chain launch

__device__ float g_bufA[NPL*PLANE];
__device__ float g_bufB[NPL*PLANE];
__device__ float g_skel[NPL*PLANE];
__device__ float g_acc[96];

// fast sigmoid: sigmoid(x) = 0.5*tanh(x/2) + 0.5  (MUFU.TANH, sm_75+)
__device__ __forceinline__ float sigmoidf_(float x) {
    float t;
    asm("tanh.approx.f32 %0, %1;" : "=f"(t) : "f"(0.5f * x));
    return fmaf(0.5f, t, 0.5f);
}

__device__ __forceinline__ float focal_elem(float x, float t) {
    float e = __expf(-fabsf(x));
    float bce = fmaxf(x, 0.0f) - x * t + __logf(1.0f + e);
    float p   = sigmoidf_(x);
    float pt  = p * t + (1.0f - p) * (1.0f - t);
    float at  = 0.25f * t + 0.75f * (1.0f - t);
    float om  = 1.0f - pt;
    return at * om * om * bce;
}

__device__ __forceinline__ float blk_sum(float v, float* sh) {
    int tid = threadIdx.x;
    #pragma unroll
    for (int o = 16; o > 0; o >>= 1) v += __shfl_down_sync(0xffffffffu, v, o);
    if ((tid & 31) == 0) sh[tid >> 5] = v;
    __syncthreads();
    float r = 0.0f;
    if (tid < 32) {
        r = (tid < (int)(blockDim.x >> 5)) ? sh[tid] : 0.0f;
        #pragma unroll
        for (int o = 16; o > 0; o >>= 1) r += __shfl_down_sync(0xffffffffu, r, o);
    }
    __syncthreads();
    return r;
}

// pairwise 5-pt cross erode over 64 warp columns (cols x0=2*lane, x1=2*lane+1)
__device__ __forceinline__ float2 erode5p(float2 m, float2 c, float2 p) {
    float lm = __shfl_up_sync(0xffffffffu, c.y, 1);
    float rm = __shfl_down_sync(0xffffffffu, c.x, 1);
    float2 r;
    r.x = fminf(fminf(fminf(m.x, p.x), c.x), fminf(lm, c.y));
    r.y = fminf(fminf(fminf(m.y, p.y), c.y), fminf(c.x, rm));
    return r;
}
// pairwise 3x3 max (open)
__device__ __forceinline__ float2 open3p(float2 m, float2 c, float2 p) {
    float2 v;
    v.x = fmaxf(fmaxf(m.x, p.x), c.x);
    v.y = fmaxf(fmaxf(m.y, p.y), c.y);
    float lm = __shfl_up_sync(0xffffffffu, v.y, 1);
    float rm = __shfl_down_sync(0xffffffffu, v.x, 1);
    float2 r;
    r.x = fmaxf(v.x, fmaxf(lm, v.y));
    r.y = fmaxf(v.y, fmaxf(v.x, rm));
    return r;
}
__device__ __forceinline__ float2 padv(float2 v, bool rowOK, bool x0OK, bool x1OK, float pad) {
    float2 r;
    r.x = (rowOK && x0OK) ? v.x : pad;
    r.y = (rowOK && x1OK) ? v.y : pad;
    return r;
}

__global__ void zero_acc_kernel() {
    if (threadIdx.x < 96) g_acc[threadIdx.x] = 0.0f;
}

// ---------------------------------------------------------------------------
// Seed: bufA[b] = sigmoid(ml), bufA[8+b] = clip(mk).  Cheap; skel dependency.
// ---------------------------------------------------------------------------
__global__ void seed_kernel(const float4* __restrict__ ml, const float4* __restrict__ mk) {
    const int Q = PLANE / 4;
    int b = blockIdx.y;
    float4* __restrict__ bufap = (float4*)g_bufA;
    for (int i = blockIdx.x * blockDim.x + threadIdx.x; i < Q; i += gridDim.x * blockDim.x) {
        int g = b * Q + i;
        float4 xm4 = ml[g];
        float4 tm4 = mk[g];
        float4 pm4, tmc4;
        #pragma unroll
        for (int u = 0; u < 4; u++) {
            ((float*)&pm4)[u] = sigmoidf_(((float*)&xm4)[u]);
            ((float*)&tmc4)[u] = fminf(fmaxf(((float*)&tm4)[u], 0.0f), 1.0f);
        }
        bufap[g] = pm4;
        bufap[(8 + b) * Q + i] = tmc4;
    }
}

// ---------------------------------------------------------------------------
// Reductions only (no bufA writes). Runs concurrent with skeletonize chains.
// ---------------------------------------------------------------------------
__global__ void reduce_kernel(const float4* __restrict__ ml, const float4* __restrict__ sl,
                              const float4* __restrict__ ul, const float4* __restrict__ jl,
                              const float4* __restrict__ el, const float4* __restrict__ ap,
                              const float4* __restrict__ mk, const float4* __restrict__ sk,
                              const float4* __restrict__ jn, const float4* __restrict__ ep,
                              const float4* __restrict__ at, const float4* __restrict__ un) {
    const int Q = PLANE / 4;
    int b   = blockIdx.y;
    int tid = threadIdx.x;
    int base = b * Q;

    float di = 0.f, dp = 0.f, dt = 0.f;
    float si = 0.f, spp = 0.f, stt = 0.f;
    float fm = 0.f, fj = 0.f, fe = 0.f;
    float sl1 = 0.f, msum = 0.f, usum = 0.f;

    for (int i = blockIdx.x * blockDim.x + tid; i < Q; i += gridDim.x * blockDim.x) {
        int g = base + i;
        float4 xm4 = ml[g];
        float4 tm4 = mk[g];

        #pragma unroll
        for (int u = 0; u < 4; u++) {
            float xm = ((float*)&xm4)[u];
            float tm = ((float*)&tm4)[u];
            float pm = sigmoidf_(xm);
            di += pm * tm;  dp += pm;  dt += tm;
            fm += focal_elem(xm, tm);
        }

        float4 ts4 = sk[g];
        float4 ps4 = sl[g];
        float4 jl4 = jl[g], jn4 = jn[g], el4 = el[g], ep4 = ep[g];
        float4 ul4 = ul[g], un4 = un[g];
        float4 ap0 = ap[b * 2 * Q + i], ap1 = ap[b * 2 * Q + Q + i];
        float4 at0 = at[b * 2 * Q + i], at1 = at[b * 2 * Q + Q + i];

        #pragma unroll
        for (int u = 0; u < 4; u++) {
            float ts = ((float*)&ts4)[u];
            float psk = sigmoidf_(((float*)&ps4)[u]);
            si += psk * ts;  spp += psk;  stt += ts;

            fj += focal_elem(((float*)&jl4)[u], ((float*)&jn4)[u]);
            fe += focal_elem(((float*)&el4)[u], ((float*)&ep4)[u]);

            float pu = sigmoidf_(((float*)&ul4)[u]);
            float du = pu - ((float*)&un4)[u];
            usum += du * du;

            float m = ts;
            float d0 = ((float*)&ap0)[u] * m - ((float*)&at0)[u] * m;
            float ad0 = fabsf(d0);
            sl1 += (ad0 < 1.0f) ? 0.5f * d0 * d0 : ad0 - 0.5f;
            float d1 = ((float*)&ap1)[u] * m - ((float*)&at1)[u] * m;
            float ad1 = fabsf(d1);
            sl1 += (ad1 < 1.0f) ? 0.5f * d1 * d1 : ad1 - 0.5f;
            msum += 2.0f * m;
        }
    }

    __shared__ float sh[32];
    float vals[12] = {di, dp, dt, si, spp, stt, fm, fj, fe, sl1, msum, usum};
    #pragma unroll
    for (int k = 0; k < 12; k++) {
        float r = blk_sum(vals[k], sh);
        if (tid == 0) {
            int a = (k < 6) ? (b * 6 + k) : (42 + k);
            atomicAdd(&g_acc[a], r);
        }
    }
}

// ---------------------------------------------------------------------------
// Fused double-iteration skeletonize, 2 columns per thread, 4 planes/launch.
//  MODE 0: init + iters 1,2  (skel pure write)
//  MODE 1: two iterations     (skel RMW)
//  MODE 2: final two iters + clDice accumulation (no global writes)
// s-update: s += fmaf(-s, d, d)  (exact: s,d in [0,1] => relu redundant)
// ---------------------------------------------------------------------------
template<int MODE>
__global__ void __launch_bounds__(128, 9) skel2_kernel(int useA, int planeBase,
                                                       const float* __restrict__ ml,
                                                       const float* __restrict__ mk) {
    const float* __restrict__ cur = useA ? g_bufA : g_bufB;
    float* __restrict__ nxt = useA ? g_bufB : g_bufA;

    int lane = threadIdx.x & 31;
    int wg = blockIdx.x * BLK_WARPS + (threadIdx.x >> 5);
    int plane = planeBase + wg / WARPS_PLANE;
    int rem = wg % WARPS_PLANE;
    int strip = rem / SEGSP;
    int seg = rem & (SEGSP - 1);

    int x0 = strip * 56 - 4 + 2 * lane;
    int x1 = x0 + 1;
    bool x0OK = (unsigned)x0 < (unsigned)W;
    bool x1OK = (unsigned)x1 < (unsigned)W;
    bool laneOut = (lane >= 2) && (lane <= 29);
    bool out0 = laneOut && x0OK;
    bool out1 = laneOut && x1OK;
    int y0 = seg * SEGH;
    int base = plane * PLANE;

    const float* __restrict__ cp = cur + base + x0;
    float* __restrict__ skp = g_skel + base + x0;
    float* __restrict__ nxp = nxt + base + x0;

    bool isPred = (plane < 8);
    int b8 = isPred ? plane : (plane - 8);
    const float* __restrict__ pp = (isPred ? mk : ml) + b8 * PLANE + x0;
    float accP = 0.0f, accS = 0.0f;

    bool fast = (strip >= 1) && (strip <= 8) && (seg >= 1) && (seg <= 30);

    float2 c0, c1, c2, c3, c4, c5;
    float2 e1_m, e1_0, e1_1, e1_2;
    float2 e2_m, e2_0, e2_1;
    float2 e3_m, e3_0;

    if (fast) {
        float2 c_[10];
        #pragma unroll
        for (int i = 0; i < 10; i++) c_[i] = *(const float2*)(cp + (y0 - 4 + i) * W);
        float2 e1r[6];
        #pragma unroll
        for (int k = 0; k < 6; k++) e1r[k] = erode5p(c_[k], c_[k + 1], c_[k + 2]);
        float2 e2r[4];
        #pragma unroll
        for (int k = 0; k < 4; k++) e2r[k] = erode5p(e1r[k], e1r[k + 1], e1r[k + 2]);
        e3_m = erode5p(e2r[0], e2r[1], e2r[2]);
        e3_0 = erode5p(e2r[1], e2r[2], e2r[3]);

        c0 = c_[4]; c1 = c_[5]; c2 = c_[6]; c3 = c_[7]; c4 = c_[8]; c5 = c_[9];
        e1_m = e1r[2]; e1_0 = e1r[3]; e1_1 = e1r[4]; e1_2 = e1r[5];
        e2_m = e2r[1]; e2_0 = e2r[2]; e2_1 = e2r[3];

        #pragma unroll 4
        for (int y = y0; y < y0 + SEGH; y++) {
            float2 c6 = *(const float2*)(cp + (y + 6) * W);
            float2 e1_3 = erode5p(c2, c3, c4);
            float2 e2_2 = erode5p(e1_1, e1_2, e1_3);
            float2 e3_1 = erode5p(e2_0, e2_1, e2_2);

            float2 openA = open3p(e2_m, e2_0, e2_1);
            float2 openB = open3p(e3_m, e3_0, e3_1);

            float2 s;
            if (MODE == 0) {
                float2 openI = open3p(e1_m, e1_0, e1_1);
                s.x = fmaxf(c0.x - openI.x, 0.0f);
                s.y = fmaxf(c0.y - openI.y, 0.0f);
            } else {
                s = *(const float2*)(skp + y * W);
            }
            float dA0 = fmaxf(e1_0.x - openA.x, 0.0f);
            float dA1 = fmaxf(e1_0.y - openA.y, 0.0f);
            s.x += fmaf(-s.x, dA0, dA0);
            s.y += fmaf(-s.y, dA1, dA1);
            float dB0 = fmaxf(e2_0.x - openB.x, 0.0f);
            float dB1 = fmaxf(e2_0.y - openB.y, 0.0f);
            s.x += fmaf(-s.x, dB0, dB0);
            s.y += fmaf(-s.y, dB1, dB1);

            if (MODE == 2) {
                if (laneOut) {
                    float2 t = *(const float2*)(pp + y * W);
                    float t0 = isPred ? fminf(fmaxf(t.x, 0.0f), 1.0f) : sigmoidf_(t.x);
                    float t1 = isPred ? fminf(fmaxf(t.y, 0.0f), 1.0f) : sigmoidf_(t.y);
                    float ps0 = fminf(fmaxf(s.x, 0.0f), 1.0f);
                    float ps1 = fminf(fmaxf(s.y, 0.0f), 1.0f);
                    accP += ps0 * t0 + ps1 * t1;
                    accS += ps0 + ps1;
                }
            } else if (laneOut) {
                *(float2*)(nxp + y * W) = e2_0;
                *(float2*)(skp + y * W) = s;
            }

            if (MODE == 0) { c0 = c1; c1 = c2; }
            c2 = c3; c3 = c4; c4 = c5; c5 = c6;
            if (MODE == 0) e1_m = e1_0;
            e1_0 = e1_1; e1_1 = e1_2; e1_2 = e1_3;
            e2_m = e2_0; e2_0 = e2_1; e2_1 = e2_2;
            e3_m = e3_0; e3_0 = e3_1;
        }
    } else {
        // ---------------- general (boundary) path ----------------
        float2 c_[10];
        #pragma unroll
        for (int i = 0; i < 10; i++) {
            int yy = y0 - 4 + i;
            bool rOK = (unsigned)yy < (unsigned)H;
            float2 v;
            v.x = (rOK && x0OK) ? cp[yy * W] : BIG;
            v.y = (rOK && x1OK) ? cp[yy * W + 1] : BIG;
            c_[i] = v;
        }
        float2 e1r[6];
        #pragma unroll
        for (int k = 0; k < 6; k++) {
            int r = y0 - 3 + k;
            e1r[k] = padv(erode5p(c_[k], c_[k + 1], c_[k + 2]),
                          (unsigned)r < (unsigned)H, x0OK, x1OK, BIG);
        }
        float2 e2r[4];
        #pragma unroll
        for (int k = 0; k < 4; k++) e2r[k] = erode5p(e1r[k], e1r[k + 1], e1r[k + 2]);

        float2 t0v = padv(e2r[0], (y0 - 2) >= 0, x0OK, x1OK, BIG);
        float2 t1v = padv(e2r[1], (y0 - 1) >= 0, x0OK, x1OK, BIG);
        float2 t2v = padv(e2r[2], true, x0OK, x1OK, BIG);
        float2 t3v = padv(e2r[3], true, x0OK, x1OK, BIG);
        e3_m = padv(erode5p(t0v, t1v, t2v), (y0 - 1) >= 0, x0OK, x1OK, -BIG);
        e3_0 = padv(erode5p(t1v, t2v, t3v), true, x0OK, x1OK, -BIG);

        c0 = c_[4]; c1 = c_[5]; c2 = c_[6]; c3 = c_[7]; c4 = c_[8]; c5 = c_[9];
        e1_m = e1r[2]; e1_0 = e1r[3]; e1_1 = e1r[4]; e1_2 = e1r[5];
        e2_m = e2r[1]; e2_0 = e2r[2]; e2_1 = e2r[3];

        #pragma unroll 4
        for (int y = y0; y < y0 + SEGH; y++) {
            int yl = y + 6;
            bool rl = (unsigned)yl < (unsigned)H;
            float2 c6;
            c6.x = (rl && x0OK) ? cp[yl * W] : BIG;
            c6.y = (rl && x1OK) ? cp[yl * W + 1] : BIG;

            float2 e1_3 = padv(erode5p(c2, c3, c4), (unsigned)(y + 3) < (unsigned)H, x0OK, x1OK, BIG);
            float2 e2_2 = erode5p(e1_1, e1_2, e1_3);

            float2 a = padv(e2_0, true, x0OK, x1OK, BIG);
            float2 b = padv(e2_1, (unsigned)(y + 1) < (unsigned)H, x0OK, x1OK, BIG);
            float2 d = padv(e2_2, (unsigned)(y + 2) < (unsigned)H, x0OK, x1OK, BIG);
            float2 e3_1 = padv(erode5p(a, b, d), (unsigned)(y + 1) < (unsigned)H, x0OK, x1OK, -BIG);

            float2 ma = padv(e2_m, (y - 1) >= 0, x0OK, x1OK, -BIG);
            float2 mb = padv(e2_0, true, x0OK, x1OK, -BIG);
            float2 mc = padv(e2_1, (unsigned)(y + 1) < (unsigned)H, x0OK, x1OK, -BIG);
            float2 openA = open3p(ma, mb, mc);
            float2 openB = open3p(e3_m, e3_0, e3_1);

            float2 s;
            if (MODE == 0) {
                float2 ia = padv(e1_m, (y - 1) >= 0, x0OK, x1OK, -BIG);
                float2 ib = padv(e1_0, true, x0OK, x1OK, -BIG);
                float2 ic = padv(e1_1, (unsigned)(y + 1) < (unsigned)H, x0OK, x1OK, -BIG);
                float2 openI = open3p(ia, ib, ic);
                s.x = fmaxf(c0.x - openI.x, 0.0f);
                s.y = fmaxf(c0.y - openI.y, 0.0f);
            } else {
                s.x = out0 ? skp[y * W] : 0.0f;
                s.y = out1 ? skp[y * W + 1] : 0.0f;
            }
            float dA0 = fmaxf(e1_0.x - openA.x, 0.0f);
            float dA1 = fmaxf(e1_0.y - openA.y, 0.0f);
            s.x += fmaf(-s.x, dA0, dA0);
            s.y += fmaf(-s.y, dA1, dA1);
            float dB0 = fmaxf(e2_0.x - openB.x, 0.0f);
            float dB1 = fmaxf(e2_0.y - openB.y, 0.0f);
            s.x += fmaf(-s.x, dB0, dB0);
            s.y += fmaf(-s.y, dB1, dB1);

            if (MODE == 2) {
                if (out0) {
                    float raw = pp[y * W];
                    float t = isPred ? fminf(fmaxf(raw, 0.0f), 1.0f) : sigmoidf_(raw);
                    float ps = fminf(fmaxf(s.x, 0.0f), 1.0f);
                    accP += ps * t;  accS += ps;
                }
                if (out1) {
                    float raw = pp[y * W + 1];
                    float t = isPred ? fminf(fmaxf(raw, 0.0f), 1.0f) : sigmoidf_(raw);
                    float ps = fminf(fmaxf(s.y, 0.0f), 1.0f);
                    accP += ps * t;  accS += ps;
                }
            } else {
                if (out0) { nxp[y * W] = e2_0.x;      skp[y * W] = s.x; }
                if (out1) { nxp[y * W + 1] = e2_0.y;  skp[y * W + 1] = s.y; }
            }

            c0 = c1; c1 = c2; c2 = c3; c3 = c4; c4 = c5; c5 = c6;
            e1_m = e1_0; e1_0 = e1_1; e1_1 = e1_2; e1_2 = e1_3;
            e2_m = e2_0; e2_0 = e2_1; e2_1 = e2_2;
            e3_m = e3_0; e3_0 = e3_1;
        }
    }

    if (MODE == 2) {
        #pragma unroll
        for (int o = 16; o > 0; o >>= 1) {
            accP += __shfl_down_sync(0xffffffffu, accP, o);
            accS += __shfl_down_sync(0xffffffffu, accS, o);
        }
        if (lane == 0) {
            int idx = 54 + b8 * 4 + (isPred ? 0 : 2);
            atomicAdd(&g_acc[idx], accP);
            atomicAdd(&g_acc[idx + 1], accS);
        }
    }
}

// ---------------------------------------------------------------------------
__global__ void finalize_kernel(float* __restrict__ out) {
    const float N = (float)NELEM;
    float dice_m = 0.f, dice_s = 0.f, cl = 0.f;
    #pragma unroll
    for (int b = 0; b < NB; b++) {
        float im = g_acc[b * 6 + 0], pm = g_acc[b * 6 + 1], tm = g_acc[b * 6 + 2];
        dice_m += (2.0f * im + EPSF) / (pm + tm + EPSF);
        float is = g_acc[b * 6 + 3], ps = g_acc[b * 6 + 4], ts = g_acc[b * 6 + 5];
        dice_s += (2.0f * is + EPSF) / (ps + ts + EPSF);
        float c0 = g_acc[54 + b * 4 + 0], c1 = g_acc[54 + b * 4 + 1];
        float c2 = g_acc[54 + b * 4 + 2], c3 = g_acc[54 + b * 4 + 3];
        float prec = c0 / (c1 + EPSF);
        float sens = c2 / (c3 + EPSF);
        cl += (2.0f * prec * sens + EPSF) / (prec + sens + EPSF);
    }
    dice_m *= 0.125f;  dice_s *= 0.125f;  cl *= 0.125f;

    float mask_loss     = (1.0f - dice_m) + g_acc[48] / N;
    float skeleton_loss = 1.0f - dice_s;
    float topology_loss = 1.0f - cl;
    float node_loss     = 0.5f * (g_acc[49] / N + g_acc[50] / N);
    float msum          = g_acc[52];
    float aff_loss      = (msum == 0.0f) ? 0.0f : g_acc[51] / fmaxf(msum, 1.0f);
    float unc_loss      = g_acc[53] / N;

    out[0] = 1.0f * mask_loss + 1.0f * skeleton_loss + 0.5f * topology_loss +
             0.5f * node_loss + 0.5f * aff_loss + 0.1f * unc_loss;
}

// ---------------------------------------------------------------------------
extern "C" void kernel_launch(void* const* d_in, const int* in_sizes, int n_in,
                              void* d_out, int out_size) {
    const float* ml = (const float*)d_in[0];
    const float* mk = (const float*)d_in[6];
    float* out = (float*)d_out;

    zero_acc_kernel<<<1, 96>>>();

    // seed bufA (the only skel dependency)
    dim3 gS(64, NB);
    seed_kernel<<<gS, 256>>>((const float4*)d_in[0], (const float4*)d_in[6]);

    // ---- fork 4 skel chains (planes 4c..4c+3 each) ----
    const int NCH = 4;
    cudaStream_t st[NCH];
    cudaEvent_t evFork, evJoin[NCH];
    cudaEventCreateWithFlags(&evFork, cudaEventDisableTiming);
    cudaEventRecord(evFork, 0);

    for (int c = 0; c < NCH; c++) {
        cudaStreamCreateWithFlags(&st[c], cudaStreamNonBlocking);
        cudaEventCreateWithFlags(&evJoin[c], cudaEventDisableTiming);
        cudaStreamWaitEvent(st[c], evFork, 0);
        int pb = c * PL_CHUNK;
        skel2_kernel<0><<<GRIDC, 128, 0, st[c]>>>(1, pb, ml, mk);
        skel2_kernel<1><<<GRIDC, 128, 0, st[c]>>>(0, pb, ml, mk);
        skel2_kernel<1><<<GRIDC, 128, 0, st[c]>>>(1, pb, ml, mk);
        skel2_kernel<1><<<GRIDC, 128, 0, st[c]>>>(0, pb, ml, mk);
        skel2_kernel<2><<<GRIDC, 128, 0, st[c]>>>(1, pb, ml, mk);
        cudaEventRecord(evJoin[c], st[c]);
    }

    // reductions run concurrently with the skel chains (depend only on inputs)
    reduce_kernel<<<gS, 256>>>(
        (const float4*)d_in[0], (const float4*)d_in[1], (const float4*)d_in[2],
        (const float4*)d_in[3], (const float4*)d_in[4], (const float4*)d_in[5],
        (const float4*)d_in[6], (const float4*)d_in[7], (const float4*)d_in[8],
        (const float4*)d_in[9], (const float4*)d_in[10], (const float4*)d_in[11]);

    for (int c = 0; c < NCH; c++) {
        cudaStreamWaitEvent(0, evJoin[c], 0);
    }

    finalize_kernel<<<1, 1>>>(out);

    for (int c = 0; c < NCH; c++) {
        cudaStreamDestroy(st[c]);
        cudaEventDestroy(evJoin[c]);
    }
    cudaEventDestroy(evFork);
}

// round 17
// speedup vs baseline: 1.2205x; 1.0578x over previous
#include <cuda_runtime.h>
#include <math.h>

#define H 512
#define W 512
#define PLANE (H*W)
#define NB 8
#define NPL 16
#define NELEM (NB*PLANE)
#define EPSF 1e-6f
#define BIG 1e30f

// 2-col-per-thread skeletonize layout: 56 useful cols per warp, 16 rows per seg
#define STRIPSP 10
#define SEGSP   32
#define SEGH    16
#define BLK_WARPS 4
#define PL_CHUNK 4
#define WARPS_PLANE (STRIPSP*SEGSP)            // 320 warps per plane
#define GRIDC  (PL_CHUNK*WARPS_PLANE/BLK_WARPS)  // 320 blocks per chain launch

__device__ float g_bufA[NPL*PLANE];
__device__ float g_bufB[NPL*PLANE];
__device__ float g_skel[NPL*PLANE];
__device__ float g_acc[96];

// fast sigmoid: sigmoid(x) = 0.5*tanh(x/2) + 0.5  (MUFU.TANH, sm_75+)
__device__ __forceinline__ float sigmoidf_(float x) {
    float t;
    asm("tanh.approx.f32 %0, %1;" : "=f"(t) : "f"(0.5f * x));
    return fmaf(0.5f, t, 0.5f);
}

__device__ __forceinline__ float focal_elem(float x, float t) {
    float e = __expf(-fabsf(x));
    float bce = fmaxf(x, 0.0f) - x * t + __logf(1.0f + e);
    float p   = sigmoidf_(x);
    float pt  = p * t + (1.0f - p) * (1.0f - t);
    float at  = 0.25f * t + 0.75f * (1.0f - t);
    float om  = 1.0f - pt;
    return at * om * om * bce;
}

__device__ __forceinline__ float blk_sum(float v, float* sh) {
    int tid = threadIdx.x;
    #pragma unroll
    for (int o = 16; o > 0; o >>= 1) v += __shfl_down_sync(0xffffffffu, v, o);
    if ((tid & 31) == 0) sh[tid >> 5] = v;
    __syncthreads();
    float r = 0.0f;
    if (tid < 32) {
        r = (tid < (int)(blockDim.x >> 5)) ? sh[tid] : 0.0f;
        #pragma unroll
        for (int o = 16; o > 0; o >>= 1) r += __shfl_down_sync(0xffffffffu, r, o);
    }
    __syncthreads();
    return r;
}

// pairwise 5-pt cross erode over 64 warp columns (cols x0=2*lane, x1=2*lane+1)
__device__ __forceinline__ float2 erode5p(float2 m, float2 c, float2 p) {
    float lm = __shfl_up_sync(0xffffffffu, c.y, 1);
    float rm = __shfl_down_sync(0xffffffffu, c.x, 1);
    float2 r;
    r.x = fminf(fminf(fminf(m.x, p.x), c.x), fminf(lm, c.y));
    r.y = fminf(fminf(fminf(m.y, p.y), c.y), fminf(c.x, rm));
    return r;
}
// pairwise 3x3 max (open)
__device__ __forceinline__ float2 open3p(float2 m, float2 c, float2 p) {
    float2 v;
    v.x = fmaxf(fmaxf(m.x, p.x), c.x);
    v.y = fmaxf(fmaxf(m.y, p.y), c.y);
    float lm = __shfl_up_sync(0xffffffffu, v.y, 1);
    float rm = __shfl_down_sync(0xffffffffu, v.x, 1);
    float2 r;
    r.x = fmaxf(v.x, fmaxf(lm, v.y));
    r.y = fmaxf(v.y, fmaxf(v.x, rm));
    return r;
}
__device__ __forceinline__ float2 padv(float2 v, bool rowOK, bool x0OK, bool x1OK, float pad) {
    float2 r;
    r.x = (rowOK && x0OK) ? v.x : pad;
    r.y = (rowOK && x1OK) ? v.y : pad;
    return r;
}
// MODE0 on-the-fly source transform: pred plane -> sigmoid, target -> clip
__device__ __forceinline__ float2 tr2(float2 v, bool isPred) {
    float2 r;
    if (isPred) {
        r.x = sigmoidf_(v.x);
        r.y = sigmoidf_(v.y);
    } else {
        r.x = fminf(fmaxf(v.x, 0.0f), 1.0f);
        r.y = fminf(fmaxf(v.y, 0.0f), 1.0f);
    }
    return r;
}

__global__ void zero_acc_kernel() {
    if (threadIdx.x < 96) g_acc[threadIdx.x] = 0.0f;
}

// ---------------------------------------------------------------------------
// Reductions only. Runs concurrent with skeletonize chains.
// ---------------------------------------------------------------------------
__global__ void reduce_kernel(const float4* __restrict__ ml, const float4* __restrict__ sl,
                              const float4* __restrict__ ul, const float4* __restrict__ jl,
                              const float4* __restrict__ el, const float4* __restrict__ ap,
                              const float4* __restrict__ mk, const float4* __restrict__ sk,
                              const float4* __restrict__ jn, const float4* __restrict__ ep,
                              const float4* __restrict__ at, const float4* __restrict__ un) {
    const int Q = PLANE / 4;
    int b   = blockIdx.y;
    int tid = threadIdx.x;
    int base = b * Q;

    float di = 0.f, dp = 0.f, dt = 0.f;
    float si = 0.f, spp = 0.f, stt = 0.f;
    float fm = 0.f, fj = 0.f, fe = 0.f;
    float sl1 = 0.f, msum = 0.f, usum = 0.f;

    for (int i = blockIdx.x * blockDim.x + tid; i < Q; i += gridDim.x * blockDim.x) {
        int g = base + i;
        float4 xm4 = ml[g];
        float4 tm4 = mk[g];

        #pragma unroll
        for (int u = 0; u < 4; u++) {
            float xm = ((float*)&xm4)[u];
            float tm = ((float*)&tm4)[u];
            float pm = sigmoidf_(xm);
            di += pm * tm;  dp += pm;  dt += tm;
            fm += focal_elem(xm, tm);
        }

        float4 ts4 = sk[g];
        float4 ps4 = sl[g];
        float4 jl4 = jl[g], jn4 = jn[g], el4 = el[g], ep4 = ep[g];
        float4 ul4 = ul[g], un4 = un[g];
        float4 ap0 = ap[b * 2 * Q + i], ap1 = ap[b * 2 * Q + Q + i];
        float4 at0 = at[b * 2 * Q + i], at1 = at[b * 2 * Q + Q + i];

        #pragma unroll
        for (int u = 0; u < 4; u++) {
            float ts = ((float*)&ts4)[u];
            float psk = sigmoidf_(((float*)&ps4)[u]);
            si += psk * ts;  spp += psk;  stt += ts;

            fj += focal_elem(((float*)&jl4)[u], ((float*)&jn4)[u]);
            fe += focal_elem(((float*)&el4)[u], ((float*)&ep4)[u]);

            float pu = sigmoidf_(((float*)&ul4)[u]);
            float du = pu - ((float*)&un4)[u];
            usum += du * du;

            float m = ts;
            float d0 = ((float*)&ap0)[u] * m - ((float*)&at0)[u] * m;
            float ad0 = fabsf(d0);
            sl1 += (ad0 < 1.0f) ? 0.5f * d0 * d0 : ad0 - 0.5f;
            float d1 = ((float*)&ap1)[u] * m - ((float*)&at1)[u] * m;
            float ad1 = fabsf(d1);
            sl1 += (ad1 < 1.0f) ? 0.5f * d1 * d1 : ad1 - 0.5f;
            msum += 2.0f * m;
        }
    }

    __shared__ float sh[32];
    float vals[12] = {di, dp, dt, si, spp, stt, fm, fj, fe, sl1, msum, usum};
    #pragma unroll
    for (int k = 0; k < 12; k++) {
        float r = blk_sum(vals[k], sh);
        if (tid == 0) {
            int a = (k < 6) ? (b * 6 + k) : (42 + k);
            atomicAdd(&g_acc[a], r);
        }
    }
}

// ---------------------------------------------------------------------------
// Fused double-iteration skeletonize, 2 columns per thread, 4 planes/launch.
//  MODE 0: init + iters 1,2; source = sigmoid(ml)/clip(mk) computed inline
//  MODE 1: two iterations     (skel RMW)
//  MODE 2: final two iters + clDice accumulation (no global writes)
// s-update: s += fmaf(-s, d, d)  (exact: s,d in [0,1] => relu redundant)
// ---------------------------------------------------------------------------
template<int MODE>
__global__ void __launch_bounds__(128, 9) skel2_kernel(int useA, int planeBase,
                                                       const float* __restrict__ ml,
                                                       const float* __restrict__ mk) {
    int lane = threadIdx.x & 31;
    int wg = blockIdx.x * BLK_WARPS + (threadIdx.x >> 5);
    int plane = planeBase + wg / WARPS_PLANE;
    int rem = wg % WARPS_PLANE;
    int strip = rem / SEGSP;
    int seg = rem & (SEGSP - 1);

    bool isPred = (plane < 8);
    int b8 = isPred ? plane : (plane - 8);

    const float* __restrict__ cur;
    float* __restrict__ nxt = useA ? g_bufB : g_bufA;
    if (MODE == 0) {
        cur = (isPred ? ml : mk);   // raw inputs, transformed at load
    } else {
        cur = useA ? g_bufA : g_bufB;
    }

    int x0 = strip * 56 - 4 + 2 * lane;
    int x1 = x0 + 1;
    bool x0OK = (unsigned)x0 < (unsigned)W;
    bool x1OK = (unsigned)x1 < (unsigned)W;
    bool laneOut = (lane >= 2) && (lane <= 29);
    bool out0 = laneOut && x0OK;
    bool out1 = laneOut && x1OK;
    int y0 = seg * SEGH;
    int base = (MODE == 0) ? (b8 * PLANE) : (plane * PLANE);

    const float* __restrict__ cp = cur + base + x0;
    float* __restrict__ skp = g_skel + plane * PLANE + x0;
    float* __restrict__ nxp = nxt + plane * PLANE + x0;

    const float* __restrict__ pp = (isPred ? mk : ml) + b8 * PLANE + x0;
    float accP = 0.0f, accS = 0.0f;

    bool fast = (strip >= 1) && (strip <= 8) && (seg >= 1) && (seg <= 30);

    float2 c0, c1, c2, c3, c4, c5;
    float2 e1_m, e1_0, e1_1, e1_2;
    float2 e2_m, e2_0, e2_1;
    float2 e3_m, e3_0;

    if (fast) {
        float2 c_[10];
        #pragma unroll
        for (int i = 0; i < 10; i++) {
            float2 v = *(const float2*)(cp + (y0 - 4 + i) * W);
            c_[i] = (MODE == 0) ? tr2(v, isPred) : v;
        }
        float2 e1r[6];
        #pragma unroll
        for (int k = 0; k < 6; k++) e1r[k] = erode5p(c_[k], c_[k + 1], c_[k + 2]);
        float2 e2r[4];
        #pragma unroll
        for (int k = 0; k < 4; k++) e2r[k] = erode5p(e1r[k], e1r[k + 1], e1r[k + 2]);
        e3_m = erode5p(e2r[0], e2r[1], e2r[2]);
        e3_0 = erode5p(e2r[1], e2r[2], e2r[3]);

        c0 = c_[4]; c1 = c_[5]; c2 = c_[6]; c3 = c_[7]; c4 = c_[8]; c5 = c_[9];
        e1_m = e1r[2]; e1_0 = e1r[3]; e1_1 = e1r[4]; e1_2 = e1r[5];
        e2_m = e2r[1]; e2_0 = e2r[2]; e2_1 = e2r[3];

        #pragma unroll 4
        for (int y = y0; y < y0 + SEGH; y++) {
            float2 c6 = *(const float2*)(cp + (y + 6) * W);
            if (MODE == 0) c6 = tr2(c6, isPred);
            float2 e1_3 = erode5p(c2, c3, c4);
            float2 e2_2 = erode5p(e1_1, e1_2, e1_3);
            float2 e3_1 = erode5p(e2_0, e2_1, e2_2);

            float2 openA = open3p(e2_m, e2_0, e2_1);
            float2 openB = open3p(e3_m, e3_0, e3_1);

            float2 s;
            if (MODE == 0) {
                float2 openI = open3p(e1_m, e1_0, e1_1);
                s.x = fmaxf(c0.x - openI.x, 0.0f);
                s.y = fmaxf(c0.y - openI.y, 0.0f);
            } else {
                s = *(const float2*)(skp + y * W);
            }
            float dA0 = fmaxf(e1_0.x - openA.x, 0.0f);
            float dA1 = fmaxf(e1_0.y - openA.y, 0.0f);
            s.x += fmaf(-s.x, dA0, dA0);
            s.y += fmaf(-s.y, dA1, dA1);
            float dB0 = fmaxf(e2_0.x - openB.x, 0.0f);
            float dB1 = fmaxf(e2_0.y - openB.y, 0.0f);
            s.x += fmaf(-s.x, dB0, dB0);
            s.y += fmaf(-s.y, dB1, dB1);

            if (MODE == 2) {
                if (laneOut) {
                    float2 t = *(const float2*)(pp + y * W);
                    float t0 = isPred ? fminf(fmaxf(t.x, 0.0f), 1.0f) : sigmoidf_(t.x);
                    float t1 = isPred ? fminf(fmaxf(t.y, 0.0f), 1.0f) : sigmoidf_(t.y);
                    float ps0 = fminf(fmaxf(s.x, 0.0f), 1.0f);
                    float ps1 = fminf(fmaxf(s.y, 0.0f), 1.0f);
                    accP += ps0 * t0 + ps1 * t1;
                    accS += ps0 + ps1;
                }
            } else if (laneOut) {
                *(float2*)(nxp + y * W) = e2_0;
                *(float2*)(skp + y * W) = s;
            }

            if (MODE == 0) { c0 = c1; c1 = c2; }
            c2 = c3; c3 = c4; c4 = c5; c5 = c6;
            if (MODE == 0) e1_m = e1_0;
            e1_0 = e1_1; e1_1 = e1_2; e1_2 = e1_3;
            e2_m = e2_0; e2_0 = e2_1; e2_1 = e2_2;
            e3_m = e3_0; e3_0 = e3_1;
        }
    } else {
        // ---------------- general (boundary) path ----------------
        float2 c_[10];
        #pragma unroll
        for (int i = 0; i < 10; i++) {
            int yy = y0 - 4 + i;
            bool rOK = (unsigned)yy < (unsigned)H;
            float2 v;
            v.x = (rOK && x0OK) ? cp[yy * W] : 0.0f;
            v.y = (rOK && x1OK) ? cp[yy * W + 1] : 0.0f;
            if (MODE == 0) v = tr2(v, isPred);
            v.x = (rOK && x0OK) ? v.x : BIG;
            v.y = (rOK && x1OK) ? v.y : BIG;
            c_[i] = v;
        }
        float2 e1r[6];
        #pragma unroll
        for (int k = 0; k < 6; k++) {
            int r = y0 - 3 + k;
            e1r[k] = padv(erode5p(c_[k], c_[k + 1], c_[k + 2]),
                          (unsigned)r < (unsigned)H, x0OK, x1OK, BIG);
        }
        float2 e2r[4];
        #pragma unroll
        for (int k = 0; k < 4; k++) e2r[k] = erode5p(e1r[k], e1r[k + 1], e1r[k + 2]);

        float2 t0v = padv(e2r[0], (y0 - 2) >= 0, x0OK, x1OK, BIG);
        float2 t1v = padv(e2r[1], (y0 - 1) >= 0, x0OK, x1OK, BIG);
        float2 t2v = padv(e2r[2], true, x0OK, x1OK, BIG);
        float2 t3v = padv(e2r[3], true, x0OK, x1OK, BIG);
        e3_m = padv(erode5p(t0v, t1v, t2v), (y0 - 1) >= 0, x0OK, x1OK, -BIG);
        e3_0 = padv(erode5p(t1v, t2v, t3v), true, x0OK, x1OK, -BIG);

        c0 = c_[4]; c1 = c_[5]; c2 = c_[6]; c3 = c_[7]; c4 = c_[8]; c5 = c_[9];
        e1_m = e1r[2]; e1_0 = e1r[3]; e1_1 = e1r[4]; e1_2 = e1r[5];
        e2_m = e2r[1]; e2_0 = e2r[2]; e2_1 = e2r[3];

        #pragma unroll 4
        for (int y = y0; y < y0 + SEGH; y++) {
            int yl = y + 6;
            bool rl = (unsigned)yl < (unsigned)H;
            float2 c6;
            c6.x = (rl && x0OK) ? cp[yl * W] : 0.0f;
            c6.y = (rl && x1OK) ? cp[yl * W + 1] : 0.0f;
            if (MODE == 0) c6 = tr2(c6, isPred);
            c6.x = (rl && x0OK) ? c6.x : BIG;
            c6.y = (rl && x1OK) ? c6.y : BIG;

            float2 e1_3 = padv(erode5p(c2, c3, c4), (unsigned)(y + 3) < (unsigned)H, x0OK, x1OK, BIG);
            float2 e2_2 = erode5p(e1_1, e1_2, e1_3);

            float2 a = padv(e2_0, true, x0OK, x1OK, BIG);
            float2 b = padv(e2_1, (unsigned)(y + 1) < (unsigned)H, x0OK, x1OK, BIG);
            float2 d = padv(e2_2, (unsigned)(y + 2) < (unsigned)H, x0OK, x1OK, BIG);
            float2 e3_1 = padv(erode5p(a, b, d), (unsigned)(y + 1) < (unsigned)H, x0OK, x1OK, -BIG);

            float2 ma = padv(e2_m, (y - 1) >= 0, x0OK, x1OK, -BIG);
            float2 mb = padv(e2_0, true, x0OK, x1OK, -BIG);
            float2 mc = padv(e2_1, (unsigned)(y + 1) < (unsigned)H, x0OK, x1OK, -BIG);
            float2 openA = open3p(ma, mb, mc);
            float2 openB = open3p(e3_m, e3_0, e3_1);

            float2 s;
            if (MODE == 0) {
                float2 ia = padv(e1_m, (y - 1) >= 0, x0OK, x1OK, -BIG);
                float2 ib = padv(e1_0, true, x0OK, x1OK, -BIG);
                float2 ic = padv(e1_1, (unsigned)(y + 1) < (unsigned)H, x0OK, x1OK, -BIG);
                float2 openI = open3p(ia, ib, ic);
                s.x = fmaxf(c0.x - openI.x, 0.0f);
                s.y = fmaxf(c0.y - openI.y, 0.0f);
            } else {
                s.x = out0 ? skp[y * W] : 0.0f;
                s.y = out1 ? skp[y * W + 1] : 0.0f;
            }
            float dA0 = fmaxf(e1_0.x - openA.x, 0.0f);
            float dA1 = fmaxf(e1_0.y - openA.y, 0.0f);
            s.x += fmaf(-s.x, dA0, dA0);
            s.y += fmaf(-s.y, dA1, dA1);
            float dB0 = fmaxf(e2_0.x - openB.x, 0.0f);
            float dB1 = fmaxf(e2_0.y - openB.y, 0.0f);
            s.x += fmaf(-s.x, dB0, dB0);
            s.y += fmaf(-s.y, dB1, dB1);

            if (MODE == 2) {
                if (out0) {
                    float raw = pp[y * W];
                    float t = isPred ? fminf(fmaxf(raw, 0.0f), 1.0f) : sigmoidf_(raw);
                    float ps = fminf(fmaxf(s.x, 0.0f), 1.0f);
                    accP += ps * t;  accS += ps;
                }
                if (out1) {
                    float raw = pp[y * W + 1];
                    float t = isPred ? fminf(fmaxf(raw, 0.0f), 1.0f) : sigmoidf_(raw);
                    float ps = fminf(fmaxf(s.y, 0.0f), 1.0f);
                    accP += ps * t;  accS += ps;
                }
            } else {
                if (out0) { nxp[y * W] = e2_0.x;      skp[y * W] = s.x; }
                if (out1) { nxp[y * W + 1] = e2_0.y;  skp[y * W + 1] = s.y; }
            }

            c0 = c1; c1 = c2; c2 = c3; c3 = c4; c4 = c5; c5 = c6;
            e1_m = e1_0; e1_0 = e1_1; e1_1 = e1_2; e1_2 = e1_3;
            e2_m = e2_0; e2_0 = e2_1; e2_1 = e2_2;
            e3_m = e3_0; e3_0 = e3_1;
        }
    }

    if (MODE == 2) {
        #pragma unroll
        for (int o = 16; o > 0; o >>= 1) {
            accP += __shfl_down_sync(0xffffffffu, accP, o);
            accS += __shfl_down_sync(0xffffffffu, accS, o);
        }
        if (lane == 0) {
            int idx = 54 + b8 * 4 + (isPred ? 0 : 2);
            atomicAdd(&g_acc[idx], accP);
            atomicAdd(&g_acc[idx + 1], accS);
        }
    }
}

// ---------------------------------------------------------------------------
__global__ void finalize_kernel(float* __restrict__ out) {
    const float N = (float)NELEM;
    float dice_m = 0.f, dice_s = 0.f, cl = 0.f;
    #pragma unroll
    for (int b = 0; b < NB; b++) {
        float im = g_acc[b * 6 + 0], pm = g_acc[b * 6 + 1], tm = g_acc[b * 6 + 2];
        dice_m += (2.0f * im + EPSF) / (pm + tm + EPSF);
        float is = g_acc[b * 6 + 3], ps = g_acc[b * 6 + 4], ts = g_acc[b * 6 + 5];
        dice_s += (2.0f * is + EPSF) / (ps + ts + EPSF);
        float c0 = g_acc[54 + b * 4 + 0], c1 = g_acc[54 + b * 4 + 1];
        float c2 = g_acc[54 + b * 4 + 2], c3 = g_acc[54 + b * 4 + 3];
        float prec = c0 / (c1 + EPSF);
        float sens = c2 / (c3 + EPSF);
        cl += (2.0f * prec * sens + EPSF) / (prec + sens + EPSF);
    }
    dice_m *= 0.125f;  dice_s *= 0.125f;  cl *= 0.125f;

    float mask_loss     = (1.0f - dice_m) + g_acc[48] / N;
    float skeleton_loss = 1.0f - dice_s;
    float topology_loss = 1.0f - cl;
    float node_loss     = 0.5f * (g_acc[49] / N + g_acc[50] / N);
    float msum          = g_acc[52];
    float aff_loss      = (msum == 0.0f) ? 0.0f : g_acc[51] / fmaxf(msum, 1.0f);
    float unc_loss      = g_acc[53] / N;

    out[0] = 1.0f * mask_loss + 1.0f * skeleton_loss + 0.5f * topology_loss +
             0.5f * node_loss + 0.5f * aff_loss + 0.1f * unc_loss;
}

// ---------------------------------------------------------------------------
extern "C" void kernel_launch(void* const* d_in, const int* in_sizes, int n_in,
                              void* d_out, int out_size) {
    const float* ml = (const float*)d_in[0];
    const float* mk = (const float*)d_in[6];
    float* out = (float*)d_out;

    zero_acc_kernel<<<1, 96>>>();

    // ---- fork 4 skel chains (planes 4c..4c+3 each); MODE0 seeds inline ----
    const int NCH = 4;
    cudaStream_t st[NCH];
    cudaEvent_t evFork, evJoin[NCH];
    cudaEventCreateWithFlags(&evFork, cudaEventDisableTiming);
    cudaEventRecord(evFork, 0);

    for (int c = 0; c < NCH; c++) {
        cudaStreamCreateWithFlags(&st[c], cudaStreamNonBlocking);
        cudaEventCreateWithFlags(&evJoin[c], cudaEventDisableTiming);
        cudaStreamWaitEvent(st[c], evFork, 0);
        int pb = c * PL_CHUNK;
        // iters 1,2 (init, reads ml/mk inline)  -> B
        skel2_kernel<0><<<GRIDC, 128, 0, st[c]>>>(1, pb, ml, mk);
        // iters 3,4  B -> A ; 5,6  A -> B ; 7,8  B -> A
        skel2_kernel<1><<<GRIDC, 128, 0, st[c]>>>(0, pb, ml, mk);
        skel2_kernel<1><<<GRIDC, 128, 0, st[c]>>>(1, pb, ml, mk);
        skel2_kernel<1><<<GRIDC, 128, 0, st[c]>>>(0, pb, ml, mk);
        // iters 9,10 + clDice reduce, read A, no writes
        skel2_kernel<2><<<GRIDC, 128, 0, st[c]>>>(1, pb, ml, mk);
        cudaEventRecord(evJoin[c], st[c]);
    }

    // reductions run concurrently with the skel chains
    dim3 gS(64, NB);
    reduce_kernel<<<gS, 256>>>(
        (const float4*)d_in[0], (const float4*)d_in[1], (const float4*)d_in[2],
        (const float4*)d_in[3], (const float4*)d_in[4], (const float4*)d_in[5],
        (const float4*)d_in[6], (const float4*)d_in[7], (const float4*)d_in[8],
        (const float4*)d_in[9], (const float4*)d_in[10], (const float4*)d_in[11]);

    for (int c = 0; c < NCH; c++) {
        cudaStreamWaitEvent(0, evJoin[c], 0);
    }

    finalize_kernel<<<1, 1>>>(out);

    for (int c = 0; c < NCH; c++) {
        cudaStreamDestroy(st[c]);
        cudaEventDestroy(evJoin[c]);
    }
    cudaEventDestroy(evFork);
}